// round 14
// baseline (speedup 1.0000x reference)
#include <cuda_runtime.h>
#include <cuda_fp16.h>
#include <cstdint>

#define BN  2
#define NP  4096
#define KN  32
#define TOK 128
#define CQ  (BN*NP)
#define RAD2 (0.16f*0.16f)
#define H1S 72    // h1 fp16 row stride (words)
#define PS2 20    // pes fp16 row stride (words) -- conflict-free for ldmatrix

// Scratch (no allocations allowed)
__device__ float    g_F1 [CQ*TOK];   // feature @ W1[0:64]
__device__ float    g_A1b[CQ*TOK];   // abs_pe @ W1[91:187] + b1
__device__ int      g_idx[CQ*KN];
__device__ unsigned g_gmax[BN*TOK];
__device__ float    g_x[CQ], g_y[CQ], g_z[CQ];   // SoA xyz
__device__ float    g_h[BN*TOK];                 // final intermediate

__device__ __forceinline__ unsigned f2ord(float f){
    unsigned u = __float_as_uint(f);
    return (u & 0x80000000u) ? ~u : (u | 0x80000000u);
}
__device__ __forceinline__ float ord2f(unsigned u){
    return __uint_as_float((u & 0x80000000u) ? (u ^ 0x80000000u) : ~u);
}
__device__ __forceinline__ unsigned packh2(float lo, float hi){
    unsigned u; asm("cvt.rn.f16x2.f32 %0, %1, %2;" : "=r"(u) : "f"(hi), "f"(lo));
    return u;
}
__device__ __forceinline__ void mma16(float* c, unsigned a0, unsigned a1,
                                      unsigned a2, unsigned a3,
                                      unsigned b0, unsigned b1){
    asm volatile("mma.sync.aligned.m16n8k16.row.col.f32.f16.f16.f32 "
        "{%0,%1,%2,%3},{%4,%5,%6,%7},{%8,%9},{%0,%1,%2,%3};"
        : "+f"(c[0]), "+f"(c[1]), "+f"(c[2]), "+f"(c[3])
        : "r"(a0), "r"(a1), "r"(a2), "r"(a3), "r"(b0), "r"(b1));
}

// ---------------------------------------------------------------------------
// Transpose xyz AoS -> SoA, init g_gmax
// ---------------------------------------------------------------------------
__global__ void transpose_kernel(const float* __restrict__ xyz){
    int i = blockIdx.x*blockDim.x + threadIdx.x;
    if (i < CQ){
        g_x[i] = xyz[i*3];
        g_y[i] = xyz[i*3+1];
        g_z[i] = xyz[i*3+2];
    }
    if (i < BN*TOK) g_gmax[i] = 0u;
}

// ---------------------------------------------------------------------------
// Fused setup, 512 threads/block:
//   warps 0-7 : weight-stationary precompute (synced via named barrier 1/256)
//   warps 8-15: ball query (SoA float4 sweeps), grid-strided over queries
// ---------------------------------------------------------------------------
__global__ __launch_bounds__(512)
void setup_kernel(const float* __restrict__ xyz,
                  const float* __restrict__ feat,
                  const float* __restrict__ W1,
                  const float* __restrict__ b1){
    extern __shared__ float psm[];
    __shared__ int s_idx[8][KN];
    const int tid = threadIdx.x;

    if (tid < 256){
        // ================= precompute role =================
        float* W1f = psm;                 // 64*128
        float* W1a = W1f + 64*TOK;        // 96*128
        float* b1s = W1a + 96*TOK;        // 128
        float* sfb = b1s + TOK;           // 4*64
        float* spb = sfb + 4*64;          // 4*96
        float* sx  = spb + 4*96;          // 12

        for (int t = tid; t < 64*TOK/4; t += 256)
            ((float4*)W1f)[t] = ((const float4*)W1)[t];
        for (int t = tid; t < 96*TOK/4; t += 256)
            ((float4*)W1a)[t] = ((const float4*)(W1 + 91*TOK))[t];
        if (tid < TOK) b1s[tid] = b1[tid];

        const int c  = tid & 127;
        const int ph = tid >> 7;       // 0..1 -> rows {2ph, 2ph+1}

        for (int rr = blockIdx.x; rr < CQ/4; rr += gridDim.x){
            int r0 = rr*4;
            asm volatile("bar.sync 1, 256;" ::: "memory");
            if (tid < 12) sx[tid] = xyz[r0*3 + tid];
            {
                int p = tid >> 6, d = tid & 63;
                sfb[p*64 + d] = feat[(size_t)(r0+p)*64 + d];
            }
            asm volatile("bar.sync 1, 256;" ::: "memory");
            for (int t = tid; t < 384; t += 256){
                int p = t / 96, cc = t % 96;
                int a = cc >> 5, kk = (cc & 31) & 15;
                float f = __expf(-0.6140226914886731f * (float)kk);
                float ang = sx[p*3 + a] * f;
                spb[p*96 + cc] = ((cc & 31) < 16) ? __sinf(ang) : __cosf(ang);
            }
            asm volatile("bar.sync 1, 256;" ::: "memory");
            float aF0 = 0.f, aF1 = 0.f;
            float aA0 = b1s[c], aA1 = aA0;
            const float* sf0 = sfb + (2*ph  )*64;
            const float* sf1 = sfb + (2*ph+1)*64;
            const float* sp0 = spb + (2*ph  )*96;
            const float* sp1 = spb + (2*ph+1)*96;
            #pragma unroll 16
            for (int d = 0; d < 64; d++){
                float wv = W1f[d*TOK + c];
                aF0 += sf0[d] * wv;
                aF1 += sf1[d] * wv;
            }
            #pragma unroll 16
            for (int d = 0; d < 96; d++){
                float wv = W1a[d*TOK + c];
                aA0 += sp0[d] * wv;
                aA1 += sp1[d] * wv;
            }
            g_F1 [(size_t)(r0+2*ph  )*TOK + c] = aF0;
            g_F1 [(size_t)(r0+2*ph+1)*TOK + c] = aF1;
            g_A1b[(size_t)(r0+2*ph  )*TOK + c] = aA0;
            g_A1b[(size_t)(r0+2*ph+1)*TOK + c] = aA1;
        }
    } else {
        // ================= neighbor role =================
        int wl   = (tid >> 5) - 8;       // 0..7
        int lane = tid & 31;
        for (int w = blockIdx.x*8 + wl; w < CQ; w += gridDim.x*8){
            int b = w >> 12, i = w & (NP-1);
            const float* xs = g_x + (size_t)b*NP;
            const float* ys = g_y + (size_t)b*NP;
            const float* zs = g_z + (size_t)b*NP;
            float cx = xs[i], cy = ys[i], cz = zs[i];
            int count = 0;
            for (int base = 0; base < NP && count < KN; base += 128){
                int j0 = base + lane*4;
                float4 xv = *(const float4*)(xs + j0);
                float4 yv = *(const float4*)(ys + j0);
                float4 zv = *(const float4*)(zs + j0);
                float dx, dy, dz;
                dx = xv.x-cx; dy = yv.x-cy; dz = zv.x-cz;
                bool h0 = (dx*dx + dy*dy + dz*dz) <= RAD2;
                dx = xv.y-cx; dy = yv.y-cy; dz = zv.y-cz;
                bool h1 = (dx*dx + dy*dy + dz*dz) <= RAD2;
                dx = xv.z-cx; dy = yv.z-cy; dz = zv.z-cz;
                bool h2 = (dx*dx + dy*dy + dz*dz) <= RAD2;
                dx = xv.w-cx; dy = yv.w-cy; dz = zv.w-cz;
                bool h3 = (dx*dx + dy*dy + dz*dz) <= RAD2;
                int nl = (int)h0 + (int)h1 + (int)h2 + (int)h3;
                int pre = nl;
                #pragma unroll
                for (int off = 1; off < 32; off <<= 1){
                    int t = __shfl_up_sync(0xFFFFFFFFu, pre, off);
                    if (lane >= off) pre += t;
                }
                int pos = count + pre - nl;
                if (h0){ if (pos < KN) s_idx[wl][pos] = j0;     pos++; }
                if (h1){ if (pos < KN) s_idx[wl][pos] = j0 + 1; pos++; }
                if (h2){ if (pos < KN) s_idx[wl][pos] = j0 + 2; pos++; }
                if (h3){ if (pos < KN) s_idx[wl][pos] = j0 + 3; pos++; }
                count += __shfl_sync(0xFFFFFFFFu, pre, 31);
            }
            __syncwarp();
            int stored = count < KN ? count : KN;
            int first  = s_idx[wl][0];
            int v = (lane < stored) ? s_idx[wl][lane] : first;
            g_idx[(size_t)w*KN + lane] = v;
            __syncwarp();
        }
    }
}

// ---------------------------------------------------------------------------
// Main kernel (unchanged from R12): 256 thr, 2 CTAs/SM, 4 queries/iter,
// fp16 mma both phases, ldmatrix/stmatrix conflict-free layouts.
// ---------------------------------------------------------------------------
__global__ __launch_bounds__(256, 2)
void main_kernel(const float* __restrict__ W1,
                 const float* __restrict__ W2){
    extern __shared__ unsigned char smraw[];
    unsigned* h1s  = (unsigned*)smraw;               // 128*72 words (fp16x2)
    unsigned* pes  = h1s + 128*H1S;                  // 128*20 words (fp16x2)
    float*    sA1b = (float*)(pes + 128*PS2);        // 4*128
    int*      sj   = (int*)(sA1b + 4*TOK);           // 4*32
    unsigned* sbmax= (unsigned*)(sj + 4*KN);         // 2*128

    const int tid  = threadIdx.x;
    const int w    = tid >> 5;
    const int lane = tid & 31;
    const int g    = lane >> 2;
    const int tig  = lane & 3;
    const int n0   = w * 16;

    const int tt    = lane >> 3;
    const int j8    = lane & 7;
    const int thalf = tt >> 1;
    const int rbase = (tt & 1)*8 + j8;
    const unsigned h1b  = (unsigned)__cvta_generic_to_shared(h1s);
    const unsigned pesb = (unsigned)__cvta_generic_to_shared(pes);
    const int sword = rbase*H1S + 4*(((2*w + thalf) ^ j8));

    sbmax[tid] = 0u;

    unsigned bw2h[8][2][2];
    #pragma unroll
    for (int kt = 0; kt < 8; kt++)
        #pragma unroll
        for (int nt = 0; nt < 2; nt++){
            int col = n0 + nt*8 + g;
            int k0 = 16*kt + 2*tig;
            bw2h[kt][nt][0] = packh2(W2[(k0    )*TOK + col], W2[(k0+1)*TOK + col]);
            bw2h[kt][nt][1] = packh2(W2[(k0 + 8)*TOK + col], W2[(k0+9)*TOK + col]);
        }
    unsigned bw1h[2][2][2];
    #pragma unroll
    for (int kt = 0; kt < 2; kt++)
        #pragma unroll
        for (int nt = 0; nt < 2; nt++){
            int col = n0 + nt*8 + g;
            int k0 = 16*kt + 2*tig;
            float v00 = (k0   < 27) ? W1[(64+k0  )*TOK + col] : 0.f;
            float v01 = (k0+1 < 27) ? W1[(64+k0+1)*TOK + col] : 0.f;
            float v10 = (k0+8 < 27) ? W1[(64+k0+8)*TOK + col] : 0.f;
            float v11 = (k0+9 < 27) ? W1[(64+k0+9)*TOK + col] : 0.f;
            bw1h[kt][nt][0] = packh2(v00, v01);
            bw1h[kt][nt][1] = packh2(v10, v11);
        }

    for (int it = blockIdx.x; it < CQ/4; it += gridDim.x){
        int q0 = it * 4;
        int b  = q0 >> 12;
        const float* f1b = g_F1 + (size_t)b*NP*TOK;
        const float* xs = g_x + (size_t)b*NP;
        const float* ys = g_y + (size_t)b*NP;
        const float* zs = g_z + (size_t)b*NP;
        __syncthreads();

        if (tid < 128){
            int r = tid, qq = r >> 5, k = r & 31;
            int q = q0 + qq, i = q & (NP-1);
            int j = g_idx[(size_t)q*KN + k];
            sj[qq*KN + k] = j;
            float vals[27];
            vals[0] = xs[j]-xs[i]; vals[1] = ys[j]-ys[i]; vals[2] = zs[j]-zs[i];
            const float fr[4] = {1.0f, 0.046415888336127795f,
                                 0.0021544346900318843f, 1.0e-4f};
            #pragma unroll
            for (int a = 0; a < 3; a++)
                #pragma unroll
                for (int f = 0; f < 4; f++){
                    float s, cc;
                    __sincosf(vals[a]*fr[f], &s, &cc);
                    vals[3 + a*8 + f]     = s;
                    vals[3 + a*8 + 4 + f] = cc;
                }
            unsigned* pr = pes + r*PS2;
            #pragma unroll
            for (int d = 0; d < 13; d++)
                pr[d] = packh2(vals[2*d], vals[2*d+1]);
            pr[13] = packh2(vals[26], 0.f);
            pr[14] = 0u; pr[15] = 0u;
        } else {
            int t2 = tid - 128;
            int qq = t2 >> 5, e = (t2 & 31)*4;
            float4 v = *(const float4*)&g_A1b[(size_t)(q0+qq)*TOK + e];
            *(float4*)&sA1b[qq*TOK + e] = v;
        }
        __syncthreads();

        #pragma unroll 1
        for (int m = 0; m < 8; m++){
            int r0 = m*16 + g, r1 = r0 + 8, qq = m >> 1;
            int j0 = sj[qq*KN + (r0 & 31)];
            int j1 = sj[qq*KN + (r1 & 31)];
            float2 f1v[2][2], a1v[2];
            #pragma unroll
            for (int nt = 0; nt < 2; nt++){
                int c0 = n0 + nt*8 + 2*tig;
                f1v[nt][0] = *(const float2*)&f1b[(size_t)j0*TOK + c0];
                f1v[nt][1] = *(const float2*)&f1b[(size_t)j1*TOK + c0];
                a1v[nt]    = *(const float2*)&sA1b[qq*TOK + c0];
            }
            float acc[2][4] = {{0,0,0,0},{0,0,0,0}};
            #pragma unroll
            for (int kt = 0; kt < 2; kt++){
                unsigned a0, a1, a2, a3;
                unsigned adr = pesb +
                    (((m*16 + rbase)*PS2 + 4*(2*kt + thalf)) << 2);
                asm volatile("ldmatrix.sync.aligned.m8n8.x4.shared.b16 {%0,%1,%2,%3}, [%4];"
                             : "=r"(a0), "=r"(a1), "=r"(a2), "=r"(a3) : "r"(adr));
                mma16(acc[0], a0, a1, a2, a3, bw1h[kt][0][0], bw1h[kt][0][1]);
                mma16(acc[1], a0, a1, a2, a3, bw1h[kt][1][0], bw1h[kt][1][1]);
            }
            unsigned v0 = packh2(fmaxf(acc[0][0]+f1v[0][0].x+a1v[0].x, 0.f),
                                 fmaxf(acc[0][1]+f1v[0][0].y+a1v[0].y, 0.f));
            unsigned v1 = packh2(fmaxf(acc[0][2]+f1v[0][1].x+a1v[0].x, 0.f),
                                 fmaxf(acc[0][3]+f1v[0][1].y+a1v[0].y, 0.f));
            unsigned v2 = packh2(fmaxf(acc[1][0]+f1v[1][0].x+a1v[1].x, 0.f),
                                 fmaxf(acc[1][1]+f1v[1][0].y+a1v[1].y, 0.f));
            unsigned v3 = packh2(fmaxf(acc[1][2]+f1v[1][1].x+a1v[1].x, 0.f),
                                 fmaxf(acc[1][3]+f1v[1][1].y+a1v[1].y, 0.f));
            unsigned adr = h1b + ((m*16*H1S + sword) << 2);
            asm volatile("stmatrix.sync.aligned.m8n8.x4.shared.b16 [%0], {%1,%2,%3,%4};"
                         :: "r"(adr), "r"(v0), "r"(v1), "r"(v2), "r"(v3) : "memory");
        }
        __syncthreads();

        #pragma unroll 1
        for (int m = 0; m < 8; m++){
            float acc[2][4] = {{0,0,0,0},{0,0,0,0}};
            #pragma unroll
            for (int kt = 0; kt < 8; kt++){
                unsigned a0, a1, a2, a3;
                unsigned adr = h1b +
                    ((m*16*H1S + rbase*H1S + 4*(((2*kt + thalf) ^ j8))) << 2);
                asm volatile("ldmatrix.sync.aligned.m8n8.x4.shared.b16 {%0,%1,%2,%3}, [%4];"
                             : "=r"(a0), "=r"(a1), "=r"(a2), "=r"(a3) : "r"(adr));
                mma16(acc[0], a0, a1, a2, a3, bw2h[kt][0][0], bw2h[kt][0][1]);
                mma16(acc[1], a0, a1, a2, a3, bw2h[kt][1][0], bw2h[kt][1][1]);
            }
            #pragma unroll
            for (int nt = 0; nt < 2; nt++){
                float m0 = fmaxf(acc[nt][0], acc[nt][2]);
                float m1 = fmaxf(acc[nt][1], acc[nt][3]);
                #pragma unroll
                for (int off = 16; off >= 4; off >>= 1){
                    m0 = fmaxf(m0, __shfl_xor_sync(0xFFFFFFFFu, m0, off));
                    m1 = fmaxf(m1, __shfl_xor_sync(0xFFFFFFFFu, m1, off));
                }
                if (lane < 4){
                    int cB = n0 + nt*8 + 2*tig;
                    atomicMax(&sbmax[b*TOK + cB    ], f2ord(m0));
                    atomicMax(&sbmax[b*TOK + cB + 1], f2ord(m1));
                }
            }
        }
    }
    __syncthreads();
    atomicMax(&g_gmax[tid], sbmax[tid]);
}

// ---------------------------------------------------------------------------
// Final, split in two col-sliced kernels (16 blocks each):
//   final1: g_h = relu((max+b2)@W3 + b3) ; final2: out = g_h@W4 + b4
// ---------------------------------------------------------------------------
__global__ __launch_bounds__(256)
void final1_kernel(const float* __restrict__ b2,
                   const float* __restrict__ W3,
                   const float* __restrict__ b3){
    int b = blockIdx.x >> 3, s = blockIdx.x & 7;
    int cl = threadIdx.x >> 4;          // 0..15 local col
    int p  = threadIdx.x & 15;          // partial index
    int c  = s*16 + cl;
    __shared__ float gbuf[TOK];
    __shared__ float part[16][17];
    if (threadIdx.x < TOK)
        gbuf[threadIdx.x] = ord2f(g_gmax[b*TOK + threadIdx.x]) + b2[threadIdx.x];
    __syncthreads();
    float acc = 0.f;
    #pragma unroll
    for (int d = p*8; d < p*8 + 8; d++) acc += gbuf[d] * W3[d*TOK + c];
    part[cl][p] = acc;
    __syncthreads();
    if (p == 0){
        float sum = b3[c];
        #pragma unroll
        for (int i2 = 0; i2 < 16; i2++) sum += part[cl][i2];
        g_h[b*TOK + c] = fmaxf(sum, 0.f);
    }
}

__global__ __launch_bounds__(256)
void final2_kernel(const float* __restrict__ W4,
                   const float* __restrict__ b4,
                   float* __restrict__ out){
    int b = blockIdx.x >> 3, s = blockIdx.x & 7;
    int cl = threadIdx.x >> 4;
    int p  = threadIdx.x & 15;
    int c  = s*16 + cl;
    __shared__ float hbuf[TOK];
    __shared__ float part[16][17];
    if (threadIdx.x < TOK) hbuf[threadIdx.x] = g_h[b*TOK + threadIdx.x];
    __syncthreads();
    float acc = 0.f;
    #pragma unroll
    for (int d = p*8; d < p*8 + 8; d++) acc += hbuf[d] * W4[d*TOK + c];
    part[cl][p] = acc;
    __syncthreads();
    if (p == 0){
        float sum = b4[c];
        #pragma unroll
        for (int i2 = 0; i2 < 16; i2++) sum += part[cl][i2];
        out[b*TOK + c] = sum;
    }
}

// ---------------------------------------------------------------------------
extern "C" void kernel_launch(void* const* d_in, const int* in_sizes, int n_in,
                              void* d_out, int out_size){
    const float* xyz  = (const float*)d_in[0];
    const float* feat = (const float*)d_in[1];
    const float* W1   = (const float*)d_in[2];
    const float* b1   = (const float*)d_in[3];
    const float* W2   = (const float*)d_in[4];
    const float* b2   = (const float*)d_in[5];
    const float* W3   = (const float*)d_in[6];
    const float* b3   = (const float*)d_in[7];
    const float* W4   = (const float*)d_in[8];
    const float* b4   = (const float*)d_in[9];
    float* out = (float*)d_out;

    const int PRE_SMEM  = (64*TOK + 96*TOK + TOK + 4*64 + 4*96 + 12)*4;
    const int MAIN_SMEM = (128*H1S + 128*PS2)*4 + 4*TOK*4 + 4*KN*4 + BN*TOK*4;
    cudaFuncSetAttribute(setup_kernel,
                         cudaFuncAttributeMaxDynamicSharedMemorySize, PRE_SMEM);
    cudaFuncSetAttribute(main_kernel,
                         cudaFuncAttributeMaxDynamicSharedMemorySize, MAIN_SMEM);

    transpose_kernel<<<(CQ+1023)/1024, 1024>>>(xyz);
    setup_kernel<<<296, 512, PRE_SMEM>>>(xyz, feat, W1, b1);
    main_kernel<<<296, 256, MAIN_SMEM>>>(W1, W2);
    final1_kernel<<<BN*8, 256>>>(b2, W3, b3);
    final2_kernel<<<BN*8, 256>>>(W4, b4, out);
}

// round 15
// speedup vs baseline: 1.1103x; 1.1103x over previous
#include <cuda_runtime.h>
#include <cuda_fp16.h>
#include <cstdint>

#define BN  2
#define NP  4096
#define KN  32
#define TOK 128
#define CQ  (BN*NP)
#define RAD2 (0.16f*0.16f)
#define H1S 72    // h1 fp16 row stride (words)
#define PS2 20    // pes fp16 row stride (words) -- conflict-free for ldmatrix

// Scratch (no allocations allowed)
__device__ float    g_F1 [CQ*TOK];   // feature @ W1[0:64]
__device__ float    g_A1b[CQ*TOK];   // abs_pe @ W1[91:187] + b1
__device__ int      g_idx[CQ*KN];
__device__ unsigned g_gmax[BN*TOK];
__device__ float    g_x[CQ], g_y[CQ], g_z[CQ];   // SoA xyz
__device__ float    g_h[BN*TOK];                 // final intermediate

__device__ __forceinline__ unsigned f2ord(float f){
    unsigned u = __float_as_uint(f);
    return (u & 0x80000000u) ? ~u : (u | 0x80000000u);
}
__device__ __forceinline__ float ord2f(unsigned u){
    return __uint_as_float((u & 0x80000000u) ? (u ^ 0x80000000u) : ~u);
}
__device__ __forceinline__ unsigned packh2(float lo, float hi){
    unsigned u; asm("cvt.rn.f16x2.f32 %0, %1, %2;" : "=r"(u) : "f"(hi), "f"(lo));
    return u;
}
__device__ __forceinline__ void mma16(float* c, unsigned a0, unsigned a1,
                                      unsigned a2, unsigned a3,
                                      unsigned b0, unsigned b1){
    asm volatile("mma.sync.aligned.m16n8k16.row.col.f32.f16.f16.f32 "
        "{%0,%1,%2,%3},{%4,%5,%6,%7},{%8,%9},{%0,%1,%2,%3};"
        : "+f"(c[0]), "+f"(c[1]), "+f"(c[2]), "+f"(c[3])
        : "r"(a0), "r"(a1), "r"(a2), "r"(a3), "r"(b0), "r"(b1));
}

// ---------------------------------------------------------------------------
// Precompute (weight-stationary) + fused transpose/init prologue (R12 shape).
// ---------------------------------------------------------------------------
__global__ __launch_bounds__(256)
void precompute_kernel(const float* __restrict__ xyz,
                       const float* __restrict__ feat,
                       const float* __restrict__ W1,
                       const float* __restrict__ b1){
    extern __shared__ float psm[];
    float* W1f = psm;                 // 64*128
    float* W1a = W1f + 64*TOK;        // 96*128
    float* b1s = W1a + 96*TOK;        // 128
    float* sfb = b1s + TOK;           // 4*64
    float* spb = sfb + 4*64;          // 4*96
    float* sx  = spb + 4*96;          // 12
    const int tid = threadIdx.x;

    // fused transpose + gmax init
    for (int i = blockIdx.x*256 + tid; i < CQ; i += gridDim.x*256){
        g_x[i] = xyz[i*3];
        g_y[i] = xyz[i*3+1];
        g_z[i] = xyz[i*3+2];
    }
    if (blockIdx.x == 0) g_gmax[tid] = 0u;   // 256 == BN*TOK

    for (int t = tid; t < 64*TOK/4; t += 256)
        ((float4*)W1f)[t] = ((const float4*)W1)[t];
    for (int t = tid; t < 96*TOK/4; t += 256)
        ((float4*)W1a)[t] = ((const float4*)(W1 + 91*TOK))[t];
    if (tid < TOK) b1s[tid] = b1[tid];

    const int c  = tid & 127;
    const int ph = tid >> 7;       // 0..1 -> rows {2ph, 2ph+1}

    for (int rr = blockIdx.x; rr < CQ/4; rr += gridDim.x){
        int r0 = rr*4;
        __syncthreads();
        if (tid < 12) sx[tid] = xyz[r0*3 + tid];
        {
            int p = tid >> 6, d = tid & 63;
            sfb[p*64 + d] = feat[(size_t)(r0+p)*64 + d];
        }
        __syncthreads();
        for (int t = tid; t < 384; t += 256){
            int p = t / 96, cc = t % 96;
            int a = cc >> 5, kk = (cc & 31) & 15;
            float f = __expf(-0.6140226914886731f * (float)kk);
            float ang = sx[p*3 + a] * f;
            spb[p*96 + cc] = ((cc & 31) < 16) ? __sinf(ang) : __cosf(ang);
        }
        __syncthreads();
        float aF0 = 0.f, aF1 = 0.f;
        float aA0 = b1s[c], aA1 = aA0;
        const float* sf0 = sfb + (2*ph  )*64;
        const float* sf1 = sfb + (2*ph+1)*64;
        const float* sp0 = spb + (2*ph  )*96;
        const float* sp1 = spb + (2*ph+1)*96;
        #pragma unroll 16
        for (int d = 0; d < 64; d++){
            float wv = W1f[d*TOK + c];
            aF0 += sf0[d] * wv;
            aF1 += sf1[d] * wv;
        }
        #pragma unroll 16
        for (int d = 0; d < 96; d++){
            float wv = W1a[d*TOK + c];
            aA0 += sp0[d] * wv;
            aA1 += sp1[d] * wv;
        }
        g_F1 [(size_t)(r0+2*ph  )*TOK + c] = aF0;
        g_F1 [(size_t)(r0+2*ph+1)*TOK + c] = aF1;
        g_A1b[(size_t)(r0+2*ph  )*TOK + c] = aA0;
        g_A1b[(size_t)(r0+2*ph+1)*TOK + c] = aA1;
    }
}

// ---------------------------------------------------------------------------
// Ball query (SoA, float4 x 128-point sweeps): first KN ascending idx, d2<=r^2
// ---------------------------------------------------------------------------
__global__ __launch_bounds__(256)
void neighbor_kernel(){
    int gtid = blockIdx.x*blockDim.x + threadIdx.x;
    int w    = gtid >> 5;
    int lane = threadIdx.x & 31;
    if (w >= CQ) return;
    int b = w >> 12, i = w & (NP-1);
    const float* xs = g_x + (size_t)b*NP;
    const float* ys = g_y + (size_t)b*NP;
    const float* zs = g_z + (size_t)b*NP;
    float cx = xs[i], cy = ys[i], cz = zs[i];
    __shared__ int s_idx[8][KN];
    int wl = threadIdx.x >> 5;
    int count = 0;
    for (int base = 0; base < NP && count < KN; base += 128){
        int j0 = base + lane*4;
        float4 xv = *(const float4*)(xs + j0);
        float4 yv = *(const float4*)(ys + j0);
        float4 zv = *(const float4*)(zs + j0);
        float dx, dy, dz;
        dx = xv.x-cx; dy = yv.x-cy; dz = zv.x-cz;
        bool h0 = (dx*dx + dy*dy + dz*dz) <= RAD2;
        dx = xv.y-cx; dy = yv.y-cy; dz = zv.y-cz;
        bool h1 = (dx*dx + dy*dy + dz*dz) <= RAD2;
        dx = xv.z-cx; dy = yv.z-cy; dz = zv.z-cz;
        bool h2 = (dx*dx + dy*dy + dz*dz) <= RAD2;
        dx = xv.w-cx; dy = yv.w-cy; dz = zv.w-cz;
        bool h3 = (dx*dx + dy*dy + dz*dz) <= RAD2;
        int nl = (int)h0 + (int)h1 + (int)h2 + (int)h3;
        int pre = nl;
        #pragma unroll
        for (int off = 1; off < 32; off <<= 1){
            int t = __shfl_up_sync(0xFFFFFFFFu, pre, off);
            if (lane >= off) pre += t;
        }
        int pos = count + pre - nl;
        if (h0){ if (pos < KN) s_idx[wl][pos] = j0;     pos++; }
        if (h1){ if (pos < KN) s_idx[wl][pos] = j0 + 1; pos++; }
        if (h2){ if (pos < KN) s_idx[wl][pos] = j0 + 2; pos++; }
        if (h3){ if (pos < KN) s_idx[wl][pos] = j0 + 3; pos++; }
        count += __shfl_sync(0xFFFFFFFFu, pre, 31);
    }
    __syncwarp();
    int stored = count < KN ? count : KN;
    int first  = s_idx[wl][0];
    int v = (lane < stored) ? s_idx[wl][lane] : first;
    g_idx[(size_t)w*KN + lane] = v;
}

// ---------------------------------------------------------------------------
// Main kernel: 256 thr, 2 CTAs/SM, 4 queries/iter, fp16 mma both phases.
// Phase-B epilogue: max accumulated in registers across all 8 m-tiles,
// ONE shuffle-reduce + atomic per nt per iteration (was per m-tile).
// ---------------------------------------------------------------------------
__global__ __launch_bounds__(256, 2)
void main_kernel(const float* __restrict__ W1,
                 const float* __restrict__ W2){
    extern __shared__ unsigned char smraw[];
    unsigned* h1s  = (unsigned*)smraw;               // 128*72 words (fp16x2)
    unsigned* pes  = h1s + 128*H1S;                  // 128*20 words (fp16x2)
    float*    sA1b = (float*)(pes + 128*PS2);        // 4*128
    int*      sj   = (int*)(sA1b + 4*TOK);           // 4*32
    unsigned* sbmax= (unsigned*)(sj + 4*KN);         // 2*128

    const int tid  = threadIdx.x;
    const int w    = tid >> 5;
    const int lane = tid & 31;
    const int g    = lane >> 2;
    const int tig  = lane & 3;
    const int n0   = w * 16;

    const int tt    = lane >> 3;
    const int j8    = lane & 7;
    const int thalf = tt >> 1;
    const int rbase = (tt & 1)*8 + j8;
    const unsigned h1b  = (unsigned)__cvta_generic_to_shared(h1s);
    const unsigned pesb = (unsigned)__cvta_generic_to_shared(pes);
    const int sword = rbase*H1S + 4*(((2*w + thalf) ^ j8));

    sbmax[tid] = 0u;

    unsigned bw2h[8][2][2];
    #pragma unroll
    for (int kt = 0; kt < 8; kt++)
        #pragma unroll
        for (int nt = 0; nt < 2; nt++){
            int col = n0 + nt*8 + g;
            int k0 = 16*kt + 2*tig;
            bw2h[kt][nt][0] = packh2(W2[(k0    )*TOK + col], W2[(k0+1)*TOK + col]);
            bw2h[kt][nt][1] = packh2(W2[(k0 + 8)*TOK + col], W2[(k0+9)*TOK + col]);
        }
    unsigned bw1h[2][2][2];
    #pragma unroll
    for (int kt = 0; kt < 2; kt++)
        #pragma unroll
        for (int nt = 0; nt < 2; nt++){
            int col = n0 + nt*8 + g;
            int k0 = 16*kt + 2*tig;
            float v00 = (k0   < 27) ? W1[(64+k0  )*TOK + col] : 0.f;
            float v01 = (k0+1 < 27) ? W1[(64+k0+1)*TOK + col] : 0.f;
            float v10 = (k0+8 < 27) ? W1[(64+k0+8)*TOK + col] : 0.f;
            float v11 = (k0+9 < 27) ? W1[(64+k0+9)*TOK + col] : 0.f;
            bw1h[kt][nt][0] = packh2(v00, v01);
            bw1h[kt][nt][1] = packh2(v10, v11);
        }

    for (int it = blockIdx.x; it < CQ/4; it += gridDim.x){
        int q0 = it * 4;
        int b  = q0 >> 12;
        const float* f1b = g_F1 + (size_t)b*NP*TOK;
        const float* xs = g_x + (size_t)b*NP;
        const float* ys = g_y + (size_t)b*NP;
        const float* zs = g_z + (size_t)b*NP;
        __syncthreads();

        if (tid < 128){
            int r = tid, qq = r >> 5, k = r & 31;
            int q = q0 + qq, i = q & (NP-1);
            int j = g_idx[(size_t)q*KN + k];
            sj[qq*KN + k] = j;
            float vals[27];
            vals[0] = xs[j]-xs[i]; vals[1] = ys[j]-ys[i]; vals[2] = zs[j]-zs[i];
            const float fr[4] = {1.0f, 0.046415888336127795f,
                                 0.0021544346900318843f, 1.0e-4f};
            #pragma unroll
            for (int a = 0; a < 3; a++)
                #pragma unroll
                for (int f = 0; f < 4; f++){
                    float s, cc;
                    __sincosf(vals[a]*fr[f], &s, &cc);
                    vals[3 + a*8 + f]     = s;
                    vals[3 + a*8 + 4 + f] = cc;
                }
            unsigned* pr = pes + r*PS2;
            #pragma unroll
            for (int d = 0; d < 13; d++)
                pr[d] = packh2(vals[2*d], vals[2*d+1]);
            pr[13] = packh2(vals[26], 0.f);
            pr[14] = 0u; pr[15] = 0u;
        } else {
            int t2 = tid - 128;
            int qq = t2 >> 5, e = (t2 & 31)*4;
            float4 v = *(const float4*)&g_A1b[(size_t)(q0+qq)*TOK + e];
            *(float4*)&sA1b[qq*TOK + e] = v;
        }
        __syncthreads();

        // ---- phase A ----
        #pragma unroll 1
        for (int m = 0; m < 8; m++){
            int r0 = m*16 + g, r1 = r0 + 8, qq = m >> 1;
            int j0 = sj[qq*KN + (r0 & 31)];
            int j1 = sj[qq*KN + (r1 & 31)];
            float2 f1v[2][2], a1v[2];
            #pragma unroll
            for (int nt = 0; nt < 2; nt++){
                int c0 = n0 + nt*8 + 2*tig;
                f1v[nt][0] = *(const float2*)&f1b[(size_t)j0*TOK + c0];
                f1v[nt][1] = *(const float2*)&f1b[(size_t)j1*TOK + c0];
                a1v[nt]    = *(const float2*)&sA1b[qq*TOK + c0];
            }
            float acc[2][4] = {{0,0,0,0},{0,0,0,0}};
            #pragma unroll
            for (int kt = 0; kt < 2; kt++){
                unsigned a0, a1, a2, a3;
                unsigned adr = pesb +
                    (((m*16 + rbase)*PS2 + 4*(2*kt + thalf)) << 2);
                asm volatile("ldmatrix.sync.aligned.m8n8.x4.shared.b16 {%0,%1,%2,%3}, [%4];"
                             : "=r"(a0), "=r"(a1), "=r"(a2), "=r"(a3) : "r"(adr));
                mma16(acc[0], a0, a1, a2, a3, bw1h[kt][0][0], bw1h[kt][0][1]);
                mma16(acc[1], a0, a1, a2, a3, bw1h[kt][1][0], bw1h[kt][1][1]);
            }
            unsigned v0 = packh2(fmaxf(acc[0][0]+f1v[0][0].x+a1v[0].x, 0.f),
                                 fmaxf(acc[0][1]+f1v[0][0].y+a1v[0].y, 0.f));
            unsigned v1 = packh2(fmaxf(acc[0][2]+f1v[0][1].x+a1v[0].x, 0.f),
                                 fmaxf(acc[0][3]+f1v[0][1].y+a1v[0].y, 0.f));
            unsigned v2 = packh2(fmaxf(acc[1][0]+f1v[1][0].x+a1v[1].x, 0.f),
                                 fmaxf(acc[1][1]+f1v[1][0].y+a1v[1].y, 0.f));
            unsigned v3 = packh2(fmaxf(acc[1][2]+f1v[1][1].x+a1v[1].x, 0.f),
                                 fmaxf(acc[1][3]+f1v[1][1].y+a1v[1].y, 0.f));
            unsigned adr = h1b + ((m*16*H1S + sword) << 2);
            asm volatile("stmatrix.sync.aligned.m8n8.x4.shared.b16 [%0], {%1,%2,%3,%4};"
                         :: "r"(adr), "r"(v0), "r"(v1), "r"(v2), "r"(v3) : "memory");
        }
        __syncthreads();

        // ---- phase B: mma, max accumulated in regs across all m-tiles ----
        float rmx[2][4];
        #pragma unroll
        for (int nt = 0; nt < 2; nt++)
            #pragma unroll
            for (int v = 0; v < 4; v++) rmx[nt][v] = -3.4e38f;

        #pragma unroll 1
        for (int m = 0; m < 8; m++){
            float acc[2][4] = {{0,0,0,0},{0,0,0,0}};
            #pragma unroll
            for (int kt = 0; kt < 8; kt++){
                unsigned a0, a1, a2, a3;
                unsigned adr = h1b +
                    ((m*16*H1S + rbase*H1S + 4*(((2*kt + thalf) ^ j8))) << 2);
                asm volatile("ldmatrix.sync.aligned.m8n8.x4.shared.b16 {%0,%1,%2,%3}, [%4];"
                             : "=r"(a0), "=r"(a1), "=r"(a2), "=r"(a3) : "r"(adr));
                mma16(acc[0], a0, a1, a2, a3, bw2h[kt][0][0], bw2h[kt][0][1]);
                mma16(acc[1], a0, a1, a2, a3, bw2h[kt][1][0], bw2h[kt][1][1]);
            }
            #pragma unroll
            for (int nt = 0; nt < 2; nt++)
                #pragma unroll
                for (int v = 0; v < 4; v++)
                    rmx[nt][v] = fmaxf(rmx[nt][v], acc[nt][v]);
        }
        // one reduce per nt per iteration
        #pragma unroll
        for (int nt = 0; nt < 2; nt++){
            float m0 = fmaxf(rmx[nt][0], rmx[nt][2]);
            float m1 = fmaxf(rmx[nt][1], rmx[nt][3]);
            #pragma unroll
            for (int off = 16; off >= 4; off >>= 1){
                m0 = fmaxf(m0, __shfl_xor_sync(0xFFFFFFFFu, m0, off));
                m1 = fmaxf(m1, __shfl_xor_sync(0xFFFFFFFFu, m1, off));
            }
            if (lane < 4){
                int cB = n0 + nt*8 + 2*tig;
                atomicMax(&sbmax[b*TOK + cB    ], f2ord(m0));
                atomicMax(&sbmax[b*TOK + cB + 1], f2ord(m1));
            }
        }
    }
    __syncthreads();
    atomicMax(&g_gmax[tid], sbmax[tid]);
}

// ---------------------------------------------------------------------------
// Final, split in two col-sliced kernels (16 blocks each).
// ---------------------------------------------------------------------------
__global__ __launch_bounds__(256)
void final1_kernel(const float* __restrict__ b2,
                   const float* __restrict__ W3,
                   const float* __restrict__ b3){
    int b = blockIdx.x >> 3, s = blockIdx.x & 7;
    int cl = threadIdx.x >> 4;
    int p  = threadIdx.x & 15;
    int c  = s*16 + cl;
    __shared__ float gbuf[TOK];
    __shared__ float part[16][17];
    if (threadIdx.x < TOK)
        gbuf[threadIdx.x] = ord2f(g_gmax[b*TOK + threadIdx.x]) + b2[threadIdx.x];
    __syncthreads();
    float acc = 0.f;
    #pragma unroll
    for (int d = p*8; d < p*8 + 8; d++) acc += gbuf[d] * W3[d*TOK + c];
    part[cl][p] = acc;
    __syncthreads();
    if (p == 0){
        float sum = b3[c];
        #pragma unroll
        for (int i2 = 0; i2 < 16; i2++) sum += part[cl][i2];
        g_h[b*TOK + c] = fmaxf(sum, 0.f);
    }
}

__global__ __launch_bounds__(256)
void final2_kernel(const float* __restrict__ W4,
                   const float* __restrict__ b4,
                   float* __restrict__ out){
    int b = blockIdx.x >> 3, s = blockIdx.x & 7;
    int cl = threadIdx.x >> 4;
    int p  = threadIdx.x & 15;
    int c  = s*16 + cl;
    __shared__ float hbuf[TOK];
    __shared__ float part[16][17];
    if (threadIdx.x < TOK) hbuf[threadIdx.x] = g_h[b*TOK + threadIdx.x];
    __syncthreads();
    float acc = 0.f;
    #pragma unroll
    for (int d = p*8; d < p*8 + 8; d++) acc += hbuf[d] * W4[d*TOK + c];
    part[cl][p] = acc;
    __syncthreads();
    if (p == 0){
        float sum = b4[c];
        #pragma unroll
        for (int i2 = 0; i2 < 16; i2++) sum += part[cl][i2];
        out[b*TOK + c] = sum;
    }
}

// ---------------------------------------------------------------------------
extern "C" void kernel_launch(void* const* d_in, const int* in_sizes, int n_in,
                              void* d_out, int out_size){
    const float* xyz  = (const float*)d_in[0];
    const float* feat = (const float*)d_in[1];
    const float* W1   = (const float*)d_in[2];
    const float* b1   = (const float*)d_in[3];
    const float* W2   = (const float*)d_in[4];
    const float* b2   = (const float*)d_in[5];
    const float* W3   = (const float*)d_in[6];
    const float* b3   = (const float*)d_in[7];
    const float* W4   = (const float*)d_in[8];
    const float* b4   = (const float*)d_in[9];
    float* out = (float*)d_out;

    const int PRE_SMEM  = (64*TOK + 96*TOK + TOK + 4*64 + 4*96 + 12)*4;
    const int MAIN_SMEM = (128*H1S + 128*PS2)*4 + 4*TOK*4 + 4*KN*4 + BN*TOK*4;
    cudaFuncSetAttribute(precompute_kernel,
                         cudaFuncAttributeMaxDynamicSharedMemorySize, PRE_SMEM);
    cudaFuncSetAttribute(main_kernel,
                         cudaFuncAttributeMaxDynamicSharedMemorySize, MAIN_SMEM);

    precompute_kernel<<<296, 256, PRE_SMEM>>>(xyz, feat, W1, b1);
    neighbor_kernel<<<CQ/8, 256>>>();
    main_kernel<<<296, 256, MAIN_SMEM>>>(W1, W2);
    final1_kernel<<<BN*8, 256>>>(b2, W3, b3);
    final2_kernel<<<BN*8, 256>>>(W4, b4, out);
}